// round 3
// baseline (speedup 1.0000x reference)
#include <cuda_runtime.h>
#include <cstdint>

#define N_NODES 100000
#define N_EDGES 1600000
#define IN_F 128
#define HID 64
#define EMB 32

// ---------------- scratch (device globals; no allocs allowed) ----------------
__device__ __align__(16) float g_xl[N_NODES * HID];    // x @ W1_l
__device__ __align__(16) float g_xr[N_NODES * HID];    // x @ W1_r
__device__ __align__(16) float g_agg1[N_NODES * HID];  // segment_sum of xl
__device__ __align__(16) float g_h[N_NODES * HID];     // layer-1 output
__device__ __align__(16) float g_hl[N_NODES * EMB];    // h @ W2_l
__device__ __align__(16) float g_hr[N_NODES * EMB];    // h @ W2_r
__device__ __align__(16) float g_agg2[N_NODES * EMB];  // segment_sum of hl
__device__ float g_cnt[N_NODES];                       // in-degree
__device__ int   g_stride;                             // 1 = int32 indices, 2 = int64

// ---------------- kernels ----------------

// Detect index dtype: int64 little-endian indices (< 2^31) have zero high
// words at every odd int32 position. Sample 4096 odd words.
__global__ void k_detect(const int* __restrict__ w) {
    __shared__ int nz;
    if (threadIdx.x == 0) nz = 0;
    __syncthreads();
    int cnt = 0;
    for (int i = threadIdx.x; i < 4096; i += blockDim.x)
        if (w[2 * i + 1] != 0) cnt++;
    atomicAdd(&nz, cnt);
    __syncthreads();
    if (threadIdx.x == 0) g_stride = (nz == 0) ? 2 : 1;
}

// Zero the accumulators (graph replays must be idempotent).
__global__ void k_zero() {
    int i = blockIdx.x * blockDim.x + threadIdx.x;
    if (i < N_NODES * HID) g_agg1[i] = 0.f;
    if (i < N_NODES * EMB) g_agg2[i] = 0.f;
    if (i < N_NODES)       g_cnt[i]  = 0.f;
}

// In-degree counts.
__global__ void k_degree(const int* __restrict__ ei) {
    int e = blockIdx.x * blockDim.x + threadIdx.x;
    if (e >= N_EDGES) return;
    int st = g_stride;
    int d = ei[((size_t)N_EDGES + e) * st];
    if ((unsigned)d < N_NODES) atomicAdd(&g_cnt[d], 1.0f);
}

// xl = x @ W1_l, xr = x @ W1_r.  One node per block, 128 threads:
// t<64 -> xl col t, t>=64 -> xr col t-64.  x row staged in smem.
__global__ void k_lin1(const float* __restrict__ x,
                       const float* __restrict__ Wl,
                       const float* __restrict__ Wr) {
    __shared__ float xs[IN_F];
    int n = blockIdx.x;
    int t = threadIdx.x;
    xs[t] = x[(size_t)n * IN_F + t];
    __syncthreads();
    int col = t & (HID - 1);
    const float* __restrict__ W = (t < HID) ? Wl : Wr;
    float acc = 0.f;
#pragma unroll 8
    for (int k = 0; k < IN_F; ++k)
        acc += xs[k] * __ldg(&W[k * HID + col]);
    float* out = (t < HID) ? g_xl : g_xr;
    out[(size_t)n * HID + col] = acc;
}

// Scatter layer 1: 16 lanes per edge; each lane float4-gathers 4 cols of
// xl[src] and atomically accumulates into agg1[dst].
__global__ void k_scatter1(const int* __restrict__ ei) {
    int gid = blockIdx.x * blockDim.x + threadIdx.x;
    int lane = gid & 15;
    int e = gid >> 4;
    if (e >= N_EDGES) return;
    int st = g_stride;
    int s = ei[(size_t)e * st];
    int d = ei[((size_t)N_EDGES + e) * st];
    if ((unsigned)s >= N_NODES || (unsigned)d >= N_NODES) return;
    const float4 v = *reinterpret_cast<const float4*>(&g_xl[(size_t)s * HID + lane * 4]);
    float* p = &g_agg1[(size_t)d * HID + lane * 4];
    atomicAdd(p + 0, v.x);
    atomicAdd(p + 1, v.y);
    atomicAdd(p + 2, v.z);
    atomicAdd(p + 3, v.w);
}

// h = relu(agg1 / max(cnt,1) + b1 + xr)
__global__ void k_finish1(const float* __restrict__ b1) {
    int i = blockIdx.x * blockDim.x + threadIdx.x;
    if (i >= N_NODES * HID) return;
    int n = i / HID, c = i - n * HID;
    float inv = 1.0f / fmaxf(g_cnt[n], 1.0f);
    float v = g_agg1[i] * inv + __ldg(&b1[c]) + g_xr[i];
    g_h[i] = fmaxf(v, 0.f);
}

// hl = h @ W2_l, hr = h @ W2_r.  One node per block, 64 threads.
__global__ void k_lin2(const float* __restrict__ Wl,
                       const float* __restrict__ Wr) {
    __shared__ float hs[HID];
    int n = blockIdx.x;
    int t = threadIdx.x;
    hs[t] = g_h[(size_t)n * HID + t];
    __syncthreads();
    int col = t & (EMB - 1);
    const float* __restrict__ W = (t < EMB) ? Wl : Wr;
    float acc = 0.f;
#pragma unroll 8
    for (int k = 0; k < HID; ++k)
        acc += hs[k] * __ldg(&W[k * EMB + col]);
    float* out = (t < EMB) ? g_hl : g_hr;
    out[(size_t)n * EMB + col] = acc;
}

// Scatter layer 2: 8 lanes per edge (32 cols).
__global__ void k_scatter2(const int* __restrict__ ei) {
    int gid = blockIdx.x * blockDim.x + threadIdx.x;
    int lane = gid & 7;
    int e = gid >> 3;
    if (e >= N_EDGES) return;
    int st = g_stride;
    int s = ei[(size_t)e * st];
    int d = ei[((size_t)N_EDGES + e) * st];
    if ((unsigned)s >= N_NODES || (unsigned)d >= N_NODES) return;
    const float4 v = *reinterpret_cast<const float4*>(&g_hl[(size_t)s * EMB + lane * 4]);
    float* p = &g_agg2[(size_t)d * EMB + lane * 4];
    atomicAdd(p + 0, v.x);
    atomicAdd(p + 1, v.y);
    atomicAdd(p + 2, v.z);
    atomicAdd(p + 3, v.w);
}

// emb = relu(agg2/max(cnt,1) + b2 + hr); risk = emb @ Wh + bh.
// One warp per node; lane c handles emb col c; butterfly-reduce the head dot.
__global__ void k_final(const float* __restrict__ b2,
                        const float* __restrict__ Wh,
                        const float* __restrict__ bh,
                        float* __restrict__ out,
                        int write_emb, long long risk_off, int write_risk) {
    int wid = (blockIdx.x * blockDim.x + threadIdx.x) >> 5;
    int lane = threadIdx.x & 31;
    if (wid >= N_NODES) return;
    int n = wid;
    float inv = 1.0f / fmaxf(g_cnt[n], 1.0f);
    size_t i = (size_t)n * EMB + lane;
    float v = g_agg2[i] * inv + __ldg(&b2[lane]) + g_hr[i];
    float emb = fmaxf(v, 0.f);
    if (write_emb) out[i] = emb;                    // embeddings block
    float p = emb * __ldg(&Wh[lane]);
#pragma unroll
    for (int off = 16; off > 0; off >>= 1)
        p += __shfl_xor_sync(0xFFFFFFFFu, p, off);
    if (write_risk && lane == 0)
        out[risk_off + n] = p + __ldg(&bh[0]);      // risk block
}

// ---------------- launch ----------------
extern "C" void kernel_launch(void* const* d_in, const int* in_sizes, int n_in,
                              void* d_out, int out_size) {
    // Bind inputs by element-count signature (robust to ordering/dtype quirks).
    const float *x = 0, *W1_l = 0, *b1 = 0, *W1_r = 0, *W2_l = 0, *b2 = 0,
                *W2_r = 0, *Wh = 0, *bh = 0;
    const int* ei = 0;
    int n8192 = 0, n2048 = 0, n32 = 0;
    for (int i = 0; i < n_in; ++i) {
        int sz = in_sizes[i];
        const void* p = d_in[i];
        if (sz == N_NODES * IN_F)                      x = (const float*)p;
        else if (sz == 2 * N_EDGES || sz == 4 * N_EDGES) ei = (const int*)p;
        else if (sz == IN_F * HID) { if (n8192++ == 0) W1_l = (const float*)p; else W1_r = (const float*)p; }
        else if (sz == HID * EMB)  { if (n2048++ == 0) W2_l = (const float*)p; else W2_r = (const float*)p; }
        else if (sz == HID)        b1 = (const float*)p;
        else if (sz == EMB)        { if (n32++ == 0) b2 = (const float*)p; else Wh = (const float*)p; }
        else if (sz == 1)          bh = (const float*)p;
    }
    float* out = (float*)d_out;

    int write_emb = (out_size >= N_NODES * EMB) ? 1 : 0;
    long long risk_off = write_emb ? (long long)N_NODES * EMB : 0;
    int write_risk = (out_size - (write_emb ? N_NODES * EMB : 0) >= N_NODES) ? 1 : 0;

    // 0) detect index dtype (int32 vs int64)
    k_detect<<<1, 256>>>(ei);
    // 1) zero accumulators
    k_zero<<<(N_NODES * HID + 255) / 256, 256>>>();
    // 2) degrees
    k_degree<<<(N_EDGES + 255) / 256, 256>>>(ei);
    // 3) layer-1 linear
    k_lin1<<<N_NODES, IN_F>>>(x, W1_l, W1_r);
    // 4) layer-1 scatter (16 lanes/edge)
    {
        long long total = (long long)N_EDGES * 16;
        k_scatter1<<<(int)((total + 255) / 256), 256>>>(ei);
    }
    // 5) layer-1 finish
    k_finish1<<<(N_NODES * HID + 255) / 256, 256>>>(b1);
    // 6) layer-2 linear
    k_lin2<<<N_NODES, HID>>>(W2_l, W2_r);
    // 7) layer-2 scatter (8 lanes/edge)
    {
        long long total = (long long)N_EDGES * 8;
        k_scatter2<<<(int)((total + 255) / 256), 256>>>(ei);
    }
    // 8) final: embeddings + risk head
    {
        int threads = 256;
        int blocks = (N_NODES * 32 + threads - 1) / threads;
        k_final<<<blocks, threads>>>(b2, Wh, bh, out, write_emb, risk_off, write_risk);
    }
}

// round 7
// speedup vs baseline: 2.2360x; 2.2360x over previous
#include <cuda_runtime.h>
#include <cstdint>

#define N_NODES 100000
#define N_EDGES 1600000
#define IN_F 128
#define HID 64
#define EMB 32

// ---------------- scratch (device globals; referenced ONLY in device code) ----
__device__ __align__(16) float g_xl[N_NODES * HID];    // x @ W1_l
__device__ __align__(16) float g_xr[N_NODES * HID];    // x @ W1_r
__device__ __align__(16) float g_agg1[N_NODES * HID];  // segment_sum of xl
__device__ __align__(16) float g_hl[N_NODES * EMB];    // h @ W2_l
__device__ __align__(16) float g_hr[N_NODES * EMB];    // h @ W2_r
__device__ __align__(16) float g_agg2[N_NODES * EMB];  // segment_sum of hl
__device__ float g_cnt[N_NODES];                       // in-degree
__device__ int   g_stride;                             // 1 = int32 indices, 2 = int64

// ---------------- helpers ----------------
__device__ __forceinline__ void red_add_v4(float* p, float a, float b, float c, float d) {
    asm volatile("red.global.add.v4.f32 [%0], {%1, %2, %3, %4};"
                 :: "l"(p), "f"(a), "f"(b), "f"(c), "f"(d) : "memory");
}

// ---------------- kernels ----------------

// Detect index dtype: int64 little-endian indices (< 2^31) have zero high
// words at every odd int32 position.
__global__ void k_detect(const int* __restrict__ w) {
    __shared__ int nz;
    if (threadIdx.x == 0) nz = 0;
    __syncthreads();
    int cnt = 0;
    for (int i = threadIdx.x; i < 4096; i += blockDim.x)
        if (w[2 * i + 1] != 0) cnt++;
    atomicAdd(&nz, cnt);
    __syncthreads();
    if (threadIdx.x == 0) g_stride = (nz == 0) ? 2 : 1;
}

// Zero the accumulators (graph replays must be idempotent).
__global__ void k_zero() {
    int i = blockIdx.x * blockDim.x + threadIdx.x;
    if (i < N_NODES * HID) g_agg1[i] = 0.f;
    if (i < N_NODES * EMB) g_agg2[i] = 0.f;
    if (i < N_NODES)       g_cnt[i]  = 0.f;
}

// Layer-1 dual GEMM: g_xl = X@Wl, g_xr = X@Wr.  MT=64 nodes/block, K chunked
// by 32 (smem 24KB). 256 threads: thread (ty,tx) -> 4 rows x 4 col-pairs,
// pair j at columns n = 2*tx + 32*j (conflict-free LDS.64 of ws; xs broadcast).
__global__ void k_gemm1(const float* __restrict__ X,
                        const float* __restrict__ Wl,
                        const float* __restrict__ Wr) {
    __shared__ __align__(16) float ws[32][128];
    __shared__ __align__(16) float xs[32][64];   // transposed: xs[k][m]

    int tid = threadIdx.x;
    int n0 = blockIdx.x * 64;
    int rows = N_NODES - n0; if (rows > 64) rows = 64;
    int ty = tid >> 4, tx = tid & 15;
    int m0 = ty * 4;

    float2 acc[4][4];
#pragma unroll
    for (int i = 0; i < 4; ++i)
#pragma unroll
        for (int j = 0; j < 4; ++j) acc[i][j] = make_float2(0.f, 0.f);

    for (int kc = 0; kc < IN_F; kc += 32) {
        for (int idx = tid; idx < 1024; idx += 256) {   // 32*128/4
            int k = idx >> 5;
            int n = (idx & 31) * 4;
            const float* src = (n < 64) ? &Wl[(kc + k) * 64 + n]
                                        : &Wr[(kc + k) * 64 + (n - 64)];
            *reinterpret_cast<float4*>(&ws[k][n]) =
                *reinterpret_cast<const float4*>(src);
        }
        for (int idx = tid; idx < 512; idx += 256) {    // 64*32/4
            int m = idx & 63;
            int kv = (idx >> 6) * 4;
            int gr = n0 + m; if (gr >= N_NODES) gr = N_NODES - 1;
            float4 v = *reinterpret_cast<const float4*>(&X[(size_t)gr * IN_F + kc + kv]);
            xs[kv + 0][m] = v.x; xs[kv + 1][m] = v.y;
            xs[kv + 2][m] = v.z; xs[kv + 3][m] = v.w;
        }
        __syncthreads();

#pragma unroll
        for (int k = 0; k < 32; ++k) {
            float xf[4];
#pragma unroll
            for (int i = 0; i < 4; ++i) xf[i] = xs[k][m0 + i];
            float2 wv[4];
#pragma unroll
            for (int j = 0; j < 4; ++j)
                wv[j] = *reinterpret_cast<const float2*>(&ws[k][2 * tx + 32 * j]);
#pragma unroll
            for (int i = 0; i < 4; ++i)
#pragma unroll
                for (int j = 0; j < 4; ++j) {
                    acc[i][j].x = fmaf(xf[i], wv[j].x, acc[i][j].x);
                    acc[i][j].y = fmaf(xf[i], wv[j].y, acc[i][j].y);
                }
        }
        __syncthreads();
    }

#pragma unroll
    for (int j = 0; j < 4; ++j) {
        int n = 2 * tx + 32 * j;
        float* dst = (n < 64) ? g_xl : g_xr;     // device refs in device code
        int col = (n < 64) ? n : n - 64;
#pragma unroll
        for (int i = 0; i < 4; ++i)
            if (m0 + i < rows)
                *reinterpret_cast<float2*>(&dst[(size_t)(n0 + m0 + i) * HID + col]) = acc[i][j];
    }
}

// Layer-2 dual GEMM with fused layer-1 finish: the X tile is
// h = relu(agg1/max(cnt,1) + b1 + xr), computed in the load stage.
// g_hl = h@W2_l, g_hr = h@W2_r.
__global__ void k_gemm2(const float* __restrict__ Wl,
                        const float* __restrict__ Wr,
                        const float* __restrict__ b1) {
    __shared__ __align__(16) float ws[32][64];
    __shared__ __align__(16) float xs[32][64];

    int tid = threadIdx.x;
    int n0 = blockIdx.x * 64;
    int rows = N_NODES - n0; if (rows > 64) rows = 64;
    int ty = tid >> 4, tx = tid & 15;
    int m0 = ty * 4;

    float2 acc[4][2];
#pragma unroll
    for (int i = 0; i < 4; ++i)
#pragma unroll
        for (int j = 0; j < 2; ++j) acc[i][j] = make_float2(0.f, 0.f);

    for (int kc = 0; kc < HID; kc += 32) {
        for (int idx = tid; idx < 512; idx += 256) {    // 32*64/4
            int k = idx >> 4;
            int n = (idx & 15) * 4;
            const float* src = (n < 32) ? &Wl[(kc + k) * 32 + n]
                                        : &Wr[(kc + k) * 32 + (n - 32)];
            *reinterpret_cast<float4*>(&ws[k][n]) =
                *reinterpret_cast<const float4*>(src);
        }
        for (int idx = tid; idx < 512; idx += 256) {
            int m = idx & 63;
            int kv = (idx >> 6) * 4;
            int gr = n0 + m; if (gr >= N_NODES) gr = N_NODES - 1;
            float inv = 1.0f / fmaxf(g_cnt[gr], 1.0f);
            float4 a = *reinterpret_cast<const float4*>(&g_agg1[(size_t)gr * HID + kc + kv]);
            float4 r = *reinterpret_cast<const float4*>(&g_xr[(size_t)gr * HID + kc + kv]);
            float4 b = *reinterpret_cast<const float4*>(&b1[kc + kv]);
            xs[kv + 0][m] = fmaxf(fmaf(a.x, inv, b.x) + r.x, 0.f);
            xs[kv + 1][m] = fmaxf(fmaf(a.y, inv, b.y) + r.y, 0.f);
            xs[kv + 2][m] = fmaxf(fmaf(a.z, inv, b.z) + r.z, 0.f);
            xs[kv + 3][m] = fmaxf(fmaf(a.w, inv, b.w) + r.w, 0.f);
        }
        __syncthreads();

#pragma unroll
        for (int k = 0; k < 32; ++k) {
            float xf[4];
#pragma unroll
            for (int i = 0; i < 4; ++i) xf[i] = xs[k][m0 + i];
            float2 wv[2];
#pragma unroll
            for (int j = 0; j < 2; ++j)
                wv[j] = *reinterpret_cast<const float2*>(&ws[k][2 * tx + 32 * j]);
#pragma unroll
            for (int i = 0; i < 4; ++i)
#pragma unroll
                for (int j = 0; j < 2; ++j) {
                    acc[i][j].x = fmaf(xf[i], wv[j].x, acc[i][j].x);
                    acc[i][j].y = fmaf(xf[i], wv[j].y, acc[i][j].y);
                }
        }
        __syncthreads();
    }

#pragma unroll
    for (int j = 0; j < 2; ++j) {
        int n = 2 * tx + 32 * j;
        float* dst = (n < 32) ? g_hl : g_hr;
        int col = (n < 32) ? n : n - 32;
#pragma unroll
        for (int i = 0; i < 4; ++i)
            if (m0 + i < rows)
                *reinterpret_cast<float2*>(&dst[(size_t)(n0 + m0 + i) * EMB + col]) = acc[i][j];
    }
}

// Scatter layer 1: 16 lanes per edge; lane L gathers cols [4L,4L+4) of xl[src],
// one red.v4 into agg1[dst]. Lane 0 also counts degree.
__global__ void k_scatter1(const int* __restrict__ ei) {
    int gid = blockIdx.x * blockDim.x + threadIdx.x;
    int lane = gid & 15;
    int e = gid >> 4;
    if (e >= N_EDGES) return;
    int st = g_stride;
    int s = ei[(size_t)e * st];
    int d = ei[((size_t)N_EDGES + e) * st];
    if ((unsigned)s >= N_NODES || (unsigned)d >= N_NODES) return;
    const float4 v = *reinterpret_cast<const float4*>(&g_xl[(size_t)s * HID + lane * 4]);
    red_add_v4(&g_agg1[(size_t)d * HID + lane * 4], v.x, v.y, v.z, v.w);
    if (lane == 0) atomicAdd(&g_cnt[d], 1.0f);
}

// Scatter layer 2: 8 lanes per edge (32 cols).
__global__ void k_scatter2(const int* __restrict__ ei) {
    int gid = blockIdx.x * blockDim.x + threadIdx.x;
    int lane = gid & 7;
    int e = gid >> 3;
    if (e >= N_EDGES) return;
    int st = g_stride;
    int s = ei[(size_t)e * st];
    int d = ei[((size_t)N_EDGES + e) * st];
    if ((unsigned)s >= N_NODES || (unsigned)d >= N_NODES) return;
    const float4 v = *reinterpret_cast<const float4*>(&g_hl[(size_t)s * EMB + lane * 4]);
    red_add_v4(&g_agg2[(size_t)d * EMB + lane * 4], v.x, v.y, v.z, v.w);
}

// emb = relu(agg2/max(cnt,1) + b2 + hr); risk = emb @ Wh + bh.
__global__ void k_final(const float* __restrict__ b2,
                        const float* __restrict__ Wh,
                        const float* __restrict__ bh,
                        float* __restrict__ out,
                        int write_emb, long long risk_off, int write_risk) {
    int wid = (blockIdx.x * blockDim.x + threadIdx.x) >> 5;
    int lane = threadIdx.x & 31;
    if (wid >= N_NODES) return;
    int n = wid;
    float inv = 1.0f / fmaxf(g_cnt[n], 1.0f);
    size_t i = (size_t)n * EMB + lane;
    float v = fmaf(g_agg2[i], inv, __ldg(&b2[lane])) + g_hr[i];
    float emb = fmaxf(v, 0.f);
    if (write_emb) out[i] = emb;
    float p = emb * __ldg(&Wh[lane]);
#pragma unroll
    for (int off = 16; off > 0; off >>= 1)
        p += __shfl_xor_sync(0xFFFFFFFFu, p, off);
    if (write_risk && lane == 0)
        out[risk_off + n] = p + __ldg(&bh[0]);
}

// ---------------- launch ----------------
extern "C" void kernel_launch(void* const* d_in, const int* in_sizes, int n_in,
                              void* d_out, int out_size) {
    // Bind inputs by element-count signature.
    const float *x = 0, *W1_l = 0, *b1 = 0, *W1_r = 0, *W2_l = 0, *b2 = 0,
                *W2_r = 0, *Wh = 0, *bh = 0;
    const int* ei = 0;
    int n8192 = 0, n2048 = 0, n32 = 0;
    for (int i = 0; i < n_in; ++i) {
        int sz = in_sizes[i];
        const void* p = d_in[i];
        if (sz == N_NODES * IN_F)                        x = (const float*)p;
        else if (sz == 2 * N_EDGES || sz == 4 * N_EDGES) ei = (const int*)p;
        else if (sz == IN_F * HID) { if (n8192++ == 0) W1_l = (const float*)p; else W1_r = (const float*)p; }
        else if (sz == HID * EMB)  { if (n2048++ == 0) W2_l = (const float*)p; else W2_r = (const float*)p; }
        else if (sz == HID)        b1 = (const float*)p;
        else if (sz == EMB)        { if (n32++ == 0) b2 = (const float*)p; else Wh = (const float*)p; }
        else if (sz == 1)          bh = (const float*)p;
    }
    float* out = (float*)d_out;

    int write_emb = (out_size >= N_NODES * EMB) ? 1 : 0;
    long long risk_off = write_emb ? (long long)N_NODES * EMB : 0;
    int write_risk = (out_size - (write_emb ? N_NODES * EMB : 0) >= N_NODES) ? 1 : 0;

    const int GEMM_BLOCKS = (N_NODES + 63) / 64;  // 1563

    // 0) detect index dtype
    k_detect<<<1, 256>>>(ei);
    // 1) zero accumulators
    k_zero<<<(N_NODES * HID + 255) / 256, 256>>>();
    // 2) layer-1 dual GEMM
    k_gemm1<<<GEMM_BLOCKS, 256>>>(x, W1_l, W1_r);
    // 3) layer-1 scatter (fused degree count)
    {
        long long total = (long long)N_EDGES * 16;
        k_scatter1<<<(int)((total + 255) / 256), 256>>>(ei);
    }
    // 4) layer-2 dual GEMM with fused layer-1 finish
    k_gemm2<<<GEMM_BLOCKS, 256>>>(W2_l, W2_r, b1);
    // 5) layer-2 scatter
    {
        long long total = (long long)N_EDGES * 8;
        k_scatter2<<<(int)((total + 255) / 256), 256>>>(ei);
    }
    // 6) final: embeddings + risk head
    {
        int threads = 256;
        int blocks = (N_NODES * 32 + threads - 1) / threads;
        k_final<<<blocks, threads>>>(b2, Wh, bh, out, write_emb, risk_off, write_risk);
    }
}